// round 13
// baseline (speedup 1.0000x reference)
#include <cuda_runtime.h>
#include <cstdint>

#define DSPIN 64
#define NPAIR (DSPIN * (DSPIN - 1) / 2)   // 2016
#define TPB 128
#define NS 2                               // samples (batch rows) per thread

// shared layout (floats): Ms[4096] | ds[64] | xs[NS*64*TPB]
#define SM_FLOATS (DSPIN * DSPIN + DSPIN + NS * DSPIN * TPB)
#define SM_BYTES  (SM_FLOATS * 4)

// ---------- packed f32x2 helpers (sm_100+ PTX) ----------
static __device__ __forceinline__ unsigned long long pack2(float lo, float hi) {
    unsigned long long r;
    asm("mov.b64 %0, {%1, %2};" : "=l"(r) : "f"(lo), "f"(hi));
    return r;
}
static __device__ __forceinline__ void unpack2(unsigned long long v, float& lo, float& hi) {
    asm("mov.b64 {%0, %1}, %2;" : "=f"(lo), "=f"(hi) : "l"(v));
}
static __device__ __forceinline__ unsigned long long fma2(unsigned long long a,
                                                          unsigned long long b,
                                                          unsigned long long c) {
    unsigned long long d;
    asm("fma.rn.f32x2 %0, %1, %2, %3;" : "=l"(d) : "l"(a), "l"(b), "l"(c));
    return d;
}
static __device__ __forceinline__ unsigned long long add2(unsigned long long a,
                                                          unsigned long long b) {
    unsigned long long d;
    asm("add.rn.f32x2 %0, %1, %2;" : "=l"(d) : "l"(a), "l"(b));
    return d;
}
static __device__ __forceinline__ float tanh_approx(float x) {
    float r;
    asm("tanh.approx.f32 %0, %1;" : "=f"(r) : "f"(x));
    return r;
}

__global__ void __launch_bounds__(TPB, 2)
ising_kernel(const float* __restrict__ Q,
             const float* __restrict__ delta,
             const float* __restrict__ x0,
             const float* __restrict__ u,
             const int* __restrict__ cptr,
             float* __restrict__ out,
             int B, int L, int write_energy)
{
    extern __shared__ float sm[];
    float* Ms = sm;                         // 64x64 symmetrized M
    float* ds = sm + DSPIN * DSPIN;         // delta
    float* xs = ds + DSPIN;                 // x state: [s][k][tid]

    const int tid = threadIdx.x;

    // ---- build symmetrized M in shared ----
    for (int i = tid; i < DSPIN * DSPIN; i += TPB) Ms[i] = 0.0f;
    if (tid < DSPIN) ds[tid] = delta[tid];
    __syncthreads();
    for (int p = tid; p < NPAIR; p += TPB) {
        int r = (int)((1.0f + sqrtf(8.0f * (float)p + 1.0f)) * 0.5f);
        while (r * (r - 1) / 2 > p) --r;
        while ((r + 1) * r / 2 <= p) ++r;
        int c = p - r * (r - 1) / 2;
        float q = Q[p];
        Ms[r * DSPIN + c] = q;
        Ms[c * DSPIN + r] = q;
    }
    __syncthreads();

    const int b0 = blockIdx.x * (TPB * NS) + tid;   // sample s handles row b0 + s*TPB
    if (b0 >= B) return;

    const float cc    = (float)(*cptr);
    const float halfc = 0.5f * cc;

    // ---- alpha[j] = delta[j] + sum_i M[j,i] x_i, packed f32x2 (j,j+1), per sample ----
    unsigned long long alpha[NS][DSPIN / 2];

    #pragma unroll
    for (int s = 0; s < NS; ++s) {
        const int b = b0 + s * TPB;
        unsigned long long xq[DSPIN / 2];           // transient packed x0
        const float4* x0r = reinterpret_cast<const float4*>(x0 + (size_t)b * DSPIN);
        float* xss = xs + s * DSPIN * TPB;
        #pragma unroll
        for (int i = 0; i < DSPIN / 4; ++i) {
            float4 v = __ldg(x0r + i);
            xq[2 * i]     = pack2(v.x, v.y);
            xq[2 * i + 1] = pack2(v.z, v.w);
            xss[(4 * i + 0) * TPB + tid] = v.x;
            xss[(4 * i + 1) * TPB + tid] = v.y;
            xss[(4 * i + 2) * TPB + tid] = v.z;
            xss[(4 * i + 3) * TPB + tid] = v.w;
        }
        // full matvec once (init only)
        #pragma unroll
        for (int p = 0; p < DSPIN / 2; ++p) {
            float av[2];
            #pragma unroll
            for (int h = 0; h < 2; ++h) {
                const int k = 2 * p + h;
                const ulonglong2* Mr = reinterpret_cast<const ulonglong2*>(Ms + (k << 6));
                unsigned long long a0 = 0ull, a1 = 0ull, a2 = 0ull, a3 = 0ull;
                #pragma unroll
                for (int q = 0; q < DSPIN / 4; ++q) {
                    ulonglong2 m = Mr[q];
                    if (q & 1) { a2 = fma2(m.x, xq[2 * q], a2); a3 = fma2(m.y, xq[2 * q + 1], a3); }
                    else       { a0 = fma2(m.x, xq[2 * q], a0); a1 = fma2(m.y, xq[2 * q + 1], a1); }
                }
                unsigned long long t = add2(add2(a0, a2), add2(a1, a3));
                float lo, hi; unpack2(t, lo, hi);
                av[h] = ds[k] + lo + hi;
            }
            alpha[s][p] = pack2(av[0], av[1]);
        }
    }

    // ---- L Gauss-Seidel sweeps (rank-1 alpha updates) ----
    for (int l = 0; l < L; ++l) {
        const float4* ur0 = reinterpret_cast<const float4*>(u + ((size_t)l * B + b0) * DSPIN);
        const float4* ur1 = reinterpret_cast<const float4*>(u + ((size_t)l * B + b0 + TPB) * DSPIN);
        float4 cur0 = __ldg(ur0), cur1 = __ldg(ur1);

        #pragma unroll
        for (int c = 0; c < DSPIN / 4; ++c) {
            float4 nxt0, nxt1;
            if (c < DSPIN / 4 - 1) { nxt0 = __ldg(ur0 + c + 1); nxt1 = __ldg(ur1 + c + 1); }

            #pragma unroll
            for (int j = 0; j < 4; ++j) {
                const int k  = c * 4 + j;
                const int qn = (((k + 1) & (DSPIN - 1)) >> 1);   // ull holding alpha[k+1]

                float al0, al1;
                { float lo, hi; unpack2(alpha[0][k >> 1], lo, hi); al0 = (k & 1) ? hi : lo; }
                { float lo, hi; unpack2(alpha[1][k >> 1], lo, hi); al1 = (k & 1) ? hi : lo; }

                float uk0 = (j & 2) ? ((j & 1) ? cur0.w : cur0.z) : ((j & 1) ? cur0.y : cur0.x);
                float uk1 = (j & 2) ? ((j & 1) ? cur1.w : cur1.z) : ((j & 1) ? cur1.y : cur1.x);

                // nx = tanh( (c/2)*tanh(alpha) + c*(0.5 - u) )
                float nx0 = tanh_approx(fmaf(halfc, tanh_approx(al0), fmaf(-cc, uk0, halfc)));
                float nx1 = tanh_approx(fmaf(halfc, tanh_approx(al1), fmaf(-cc, uk1, halfc)));

                float xo0 = xs[k * TPB + tid];
                float xo1 = xs[DSPIN * TPB + k * TPB + tid];
                xs[k * TPB + tid]               = nx0;
                xs[DSPIN * TPB + k * TPB + tid] = nx1;

                float dx0 = nx0 - xo0;
                float dx1 = nx1 - xo1;
                unsigned long long d0 = pack2(dx0, dx0);
                unsigned long long d1 = pack2(dx1, dx1);

                // rank-1: alpha[j] += M[j,k]*dx  (M symmetric -> row k, contiguous)
                // LDS.64 loads; update the ull holding alpha[k+1] FIRST so the next
                // step's tanh chain can start while the rest issue in its shadow.
                const unsigned long long* Mr = reinterpret_cast<const unsigned long long*>(Ms + (k << 6));
                {
                    unsigned long long m = Mr[qn];
                    alpha[0][qn] = fma2(m, d0, alpha[0][qn]);
                    alpha[1][qn] = fma2(m, d1, alpha[1][qn]);
                }
                #pragma unroll
                for (int q = 0; q < DSPIN / 2; ++q) {
                    if (q == qn) continue;
                    unsigned long long m = Mr[q];
                    alpha[0][q] = fma2(m, d0, alpha[0][q]);
                    alpha[1][q] = fma2(m, d1, alpha[1][q]);
                }
            }
            if (c < DSPIN / 4 - 1) { cur0 = nxt0; cur1 = nxt1; }
        }
    }

    // ---- energy = sum_k 0.5*(alpha_k + delta_k)*x_k  (alpha_k = delta_k + (zM)_k) ----
    #pragma unroll
    for (int s = 0; s < NS; ++s) {
        const int b = b0 + s * TPB;
        const float* xss = xs + s * DSPIN * TPB;
        float energy = 0.0f;
        #pragma unroll
        for (int p = 0; p < DSPIN / 2; ++p) {
            float a_lo, a_hi; unpack2(alpha[s][p], a_lo, a_hi);
            float x_lo = xss[(2 * p) * TPB + tid];
            float x_hi = xss[(2 * p + 1) * TPB + tid];
            energy = fmaf(0.5f * (a_lo + ds[2 * p]),     x_lo, energy);
            energy = fmaf(0.5f * (a_hi + ds[2 * p + 1]), x_hi, energy);
        }

        float4* zrow = reinterpret_cast<float4*>(out + (size_t)b * DSPIN);
        #pragma unroll
        for (int i = 0; i < DSPIN / 4; ++i) {
            float4 v;
            v.x = xss[(4 * i + 0) * TPB + tid];
            v.y = xss[(4 * i + 1) * TPB + tid];
            v.z = xss[(4 * i + 2) * TPB + tid];
            v.w = xss[(4 * i + 3) * TPB + tid];
            zrow[i] = v;
        }
        if (write_energy) out[(size_t)B * DSPIN + b] = energy;
    }
}

extern "C" void kernel_launch(void* const* d_in, const int* in_sizes, int n_in,
                              void* d_out, int out_size)
{
    // metadata order: inputs, Q, delta, x0, u, n_layers, const
    const float* Q     = (const float*)d_in[1];
    const float* delta = (const float*)d_in[2];
    const float* x0    = (const float*)d_in[3];
    const float* u     = (const float*)d_in[4];
    const int*   cptr  = (const int*)d_in[6];

    const int B = in_sizes[3] / DSPIN;
    const int L = (int)((long long)in_sizes[4] / ((long long)B * DSPIN));
    const int write_energy = (out_size >= B * DSPIN + B) ? 1 : 0;

    cudaFuncSetAttribute(ising_kernel,
                         cudaFuncAttributeMaxDynamicSharedMemorySize, SM_BYTES);

    dim3 grid((B + TPB * NS - 1) / (TPB * NS));
    ising_kernel<<<grid, TPB, SM_BYTES>>>(Q, delta, x0, u, cptr, (float*)d_out,
                                          B, L, write_energy);
}

// round 14
// speedup vs baseline: 1.5000x; 1.5000x over previous
#include <cuda_runtime.h>
#include <cstdint>

#define DSPIN 64
#define NPAIR (DSPIN * (DSPIN - 1) / 2)   // 2016
#define TPB 128
#define NS 2                               // samples (batch rows) per thread

// shared layout (floats): Ms[4096] | ds[64] | xs[NS*64*TPB]
#define SM_FLOATS (DSPIN * DSPIN + DSPIN + NS * DSPIN * TPB)
#define SM_BYTES  (SM_FLOATS * 4)

// ---------- packed f32x2 helpers (sm_100+ PTX) ----------
static __device__ __forceinline__ unsigned long long pack2(float lo, float hi) {
    unsigned long long r;
    asm("mov.b64 %0, {%1, %2};" : "=l"(r) : "f"(lo), "f"(hi));
    return r;
}
static __device__ __forceinline__ void unpack2(unsigned long long v, float& lo, float& hi) {
    asm("mov.b64 {%0, %1}, %2;" : "=f"(lo), "=f"(hi) : "l"(v));
}
static __device__ __forceinline__ unsigned long long fma2(unsigned long long a,
                                                          unsigned long long b,
                                                          unsigned long long c) {
    unsigned long long d;
    asm("fma.rn.f32x2 %0, %1, %2, %3;" : "=l"(d) : "l"(a), "l"(b), "l"(c));
    return d;
}
static __device__ __forceinline__ unsigned long long add2(unsigned long long a,
                                                          unsigned long long b) {
    unsigned long long d;
    asm("add.rn.f32x2 %0, %1, %2;" : "=l"(d) : "l"(a), "l"(b));
    return d;
}
static __device__ __forceinline__ float tanh_approx(float x) {
    float r;
    asm("tanh.approx.f32 %0, %1;" : "=f"(r) : "f"(x));
    return r;
}

__global__ void __launch_bounds__(TPB, 2)
ising_kernel(const float* __restrict__ Q,
             const float* __restrict__ delta,
             const float* __restrict__ x0,
             const float* __restrict__ u,
             const int* __restrict__ cptr,
             float* __restrict__ out,
             int B, int L, int write_energy)
{
    extern __shared__ float sm[];
    float* Ms = sm;                         // 64x64 symmetrized M
    float* ds = sm + DSPIN * DSPIN;         // delta
    float* xs = ds + DSPIN;                 // x state: [s][k][tid]

    const int tid = threadIdx.x;

    // ---- build symmetrized M in shared ----
    for (int i = tid; i < DSPIN * DSPIN; i += TPB) Ms[i] = 0.0f;
    if (tid < DSPIN) ds[tid] = delta[tid];
    __syncthreads();
    for (int p = tid; p < NPAIR; p += TPB) {
        int r = (int)((1.0f + sqrtf(8.0f * (float)p + 1.0f)) * 0.5f);
        while (r * (r - 1) / 2 > p) --r;
        while ((r + 1) * r / 2 <= p) ++r;
        int c = p - r * (r - 1) / 2;
        float q = Q[p];
        Ms[r * DSPIN + c] = q;
        Ms[c * DSPIN + r] = q;
    }
    __syncthreads();

    const int b0 = blockIdx.x * (TPB * NS) + tid;   // sample s handles row b0 + s*TPB
    if (b0 >= B) return;

    const float cc    = (float)(*cptr);
    const float halfc = 0.5f * cc;

    // ---- alpha[j] = delta[j] + sum_i M[j,i] x_i, packed f32x2 (j,j+1), per sample ----
    unsigned long long alpha[NS][DSPIN / 2];

    #pragma unroll
    for (int s = 0; s < NS; ++s) {
        const int b = b0 + s * TPB;
        unsigned long long xq[DSPIN / 2];           // transient packed x0
        const float4* x0r = reinterpret_cast<const float4*>(x0 + (size_t)b * DSPIN);
        float* xss = xs + s * DSPIN * TPB;
        #pragma unroll
        for (int i = 0; i < DSPIN / 4; ++i) {
            float4 v = __ldg(x0r + i);
            xq[2 * i]     = pack2(v.x, v.y);
            xq[2 * i + 1] = pack2(v.z, v.w);
            xss[(4 * i + 0) * TPB + tid] = v.x;
            xss[(4 * i + 1) * TPB + tid] = v.y;
            xss[(4 * i + 2) * TPB + tid] = v.z;
            xss[(4 * i + 3) * TPB + tid] = v.w;
        }
        // full matvec once (init only)
        #pragma unroll
        for (int p = 0; p < DSPIN / 2; ++p) {
            float av[2];
            #pragma unroll
            for (int h = 0; h < 2; ++h) {
                const int k = 2 * p + h;
                const ulonglong2* Mr = reinterpret_cast<const ulonglong2*>(Ms + (k << 6));
                unsigned long long a0 = 0ull, a1 = 0ull, a2 = 0ull, a3 = 0ull;
                #pragma unroll
                for (int q = 0; q < DSPIN / 4; ++q) {
                    ulonglong2 m = Mr[q];
                    if (q & 1) { a2 = fma2(m.x, xq[2 * q], a2); a3 = fma2(m.y, xq[2 * q + 1], a3); }
                    else       { a0 = fma2(m.x, xq[2 * q], a0); a1 = fma2(m.y, xq[2 * q + 1], a1); }
                }
                unsigned long long t = add2(add2(a0, a2), add2(a1, a3));
                float lo, hi; unpack2(t, lo, hi);
                av[h] = ds[k] + lo + hi;
            }
            alpha[s][p] = pack2(av[0], av[1]);
        }
    }

    // ---- L Gauss-Seidel sweeps (rank-1 alpha updates) ----
    for (int l = 0; l < L; ++l) {
        const float4* ur0 = reinterpret_cast<const float4*>(u + ((size_t)l * B + b0) * DSPIN);
        const float4* ur1 = reinterpret_cast<const float4*>(u + ((size_t)l * B + b0 + TPB) * DSPIN);
        float4 cur0 = __ldg(ur0), cur1 = __ldg(ur1);

        #pragma unroll
        for (int c = 0; c < DSPIN / 4; ++c) {
            float4 nxt0, nxt1;
            if (c < DSPIN / 4 - 1) { nxt0 = __ldg(ur0 + c + 1); nxt1 = __ldg(ur1 + c + 1); }

            #pragma unroll
            for (int j = 0; j < 4; ++j) {
                const int k   = c * 4 + j;
                const int qn2 = ((k + 1) & (DSPIN - 1)) >> 2;    // ulonglong2 slice holding alpha[k+1]

                // hoist xo loads (LDS 29 cyc) so they overlap the tanh chain
                float xo0 = xs[k * TPB + tid];
                float xo1 = xs[DSPIN * TPB + k * TPB + tid];

                float al0, al1;
                { float lo, hi; unpack2(alpha[0][k >> 1], lo, hi); al0 = (k & 1) ? hi : lo; }
                { float lo, hi; unpack2(alpha[1][k >> 1], lo, hi); al1 = (k & 1) ? hi : lo; }

                float uk0 = (j & 2) ? ((j & 1) ? cur0.w : cur0.z) : ((j & 1) ? cur0.y : cur0.x);
                float uk1 = (j & 2) ? ((j & 1) ? cur1.w : cur1.z) : ((j & 1) ? cur1.y : cur1.x);

                // nx = tanh( (c/2)*tanh(alpha) + c*(0.5 - u) )
                float nx0 = tanh_approx(fmaf(halfc, tanh_approx(al0), fmaf(-cc, uk0, halfc)));
                float nx1 = tanh_approx(fmaf(halfc, tanh_approx(al1), fmaf(-cc, uk1, halfc)));

                xs[k * TPB + tid]               = nx0;
                xs[DSPIN * TPB + k * TPB + tid] = nx1;

                float dx0 = nx0 - xo0;
                float dx1 = nx1 - xo1;
                unsigned long long d0 = pack2(dx0, dx0);
                unsigned long long d1 = pack2(dx1, dx1);

                // rank-1: alpha[j] += M[j,k]*dx  (M symmetric -> row k, contiguous)
                // Update the slice holding alpha[k+1] FIRST so step k+1's tanh
                // chain launches while the remaining updates retire in its shadow.
                const ulonglong2* Mr = reinterpret_cast<const ulonglong2*>(Ms + (k << 6));
                {
                    ulonglong2 m = Mr[qn2];
                    alpha[0][2 * qn2]     = fma2(m.x, d0, alpha[0][2 * qn2]);
                    alpha[0][2 * qn2 + 1] = fma2(m.y, d0, alpha[0][2 * qn2 + 1]);
                    alpha[1][2 * qn2]     = fma2(m.x, d1, alpha[1][2 * qn2]);
                    alpha[1][2 * qn2 + 1] = fma2(m.y, d1, alpha[1][2 * qn2 + 1]);
                }
                #pragma unroll
                for (int q = 0; q < DSPIN / 4; ++q) {
                    if (q == qn2) continue;
                    ulonglong2 m = Mr[q];
                    alpha[0][2 * q]     = fma2(m.x, d0, alpha[0][2 * q]);
                    alpha[0][2 * q + 1] = fma2(m.y, d0, alpha[0][2 * q + 1]);
                    alpha[1][2 * q]     = fma2(m.x, d1, alpha[1][2 * q]);
                    alpha[1][2 * q + 1] = fma2(m.y, d1, alpha[1][2 * q + 1]);
                }
            }
            if (c < DSPIN / 4 - 1) { cur0 = nxt0; cur1 = nxt1; }
        }
    }

    // ---- energy = sum_k 0.5*(alpha_k + delta_k)*x_k  (alpha_k = delta_k + (zM)_k) ----
    #pragma unroll
    for (int s = 0; s < NS; ++s) {
        const int b = b0 + s * TPB;
        const float* xss = xs + s * DSPIN * TPB;
        float energy = 0.0f;
        #pragma unroll
        for (int p = 0; p < DSPIN / 2; ++p) {
            float a_lo, a_hi; unpack2(alpha[s][p], a_lo, a_hi);
            float x_lo = xss[(2 * p) * TPB + tid];
            float x_hi = xss[(2 * p + 1) * TPB + tid];
            energy = fmaf(0.5f * (a_lo + ds[2 * p]),     x_lo, energy);
            energy = fmaf(0.5f * (a_hi + ds[2 * p + 1]), x_hi, energy);
        }

        float4* zrow = reinterpret_cast<float4*>(out + (size_t)b * DSPIN);
        #pragma unroll
        for (int i = 0; i < DSPIN / 4; ++i) {
            float4 v;
            v.x = xss[(4 * i + 0) * TPB + tid];
            v.y = xss[(4 * i + 1) * TPB + tid];
            v.z = xss[(4 * i + 2) * TPB + tid];
            v.w = xss[(4 * i + 3) * TPB + tid];
            zrow[i] = v;
        }
        if (write_energy) out[(size_t)B * DSPIN + b] = energy;
    }
}

extern "C" void kernel_launch(void* const* d_in, const int* in_sizes, int n_in,
                              void* d_out, int out_size)
{
    // metadata order: inputs, Q, delta, x0, u, n_layers, const
    const float* Q     = (const float*)d_in[1];
    const float* delta = (const float*)d_in[2];
    const float* x0    = (const float*)d_in[3];
    const float* u     = (const float*)d_in[4];
    const int*   cptr  = (const int*)d_in[6];

    const int B = in_sizes[3] / DSPIN;
    const int L = (int)((long long)in_sizes[4] / ((long long)B * DSPIN));
    const int write_energy = (out_size >= B * DSPIN + B) ? 1 : 0;

    cudaFuncSetAttribute(ising_kernel,
                         cudaFuncAttributeMaxDynamicSharedMemorySize, SM_BYTES);

    dim3 grid((B + TPB * NS - 1) / (TPB * NS));
    ising_kernel<<<grid, TPB, SM_BYTES>>>(Q, delta, x0, u, cptr, (float*)d_out,
                                          B, L, write_energy);
}